// round 14
// baseline (speedup 1.0000x reference)
#include <cuda_runtime.h>
#include <cuda_fp16.h>
#include <stdint.h>

#define NN 100000
#define EMAX 1700000
#define FD 128
#define HD 256

// ---------------- scratch (__device__ globals; no allocs allowed) ----------
__device__ int    g_deg_out[NN];
__device__ int    g_deg_in[NN];
__device__ int    g_is64;
__device__ float  g_nsrc[NN];
__device__ float  g_ndst[NN];
__device__ int    g_rowptr[NN + 1];
__device__ int    g_cursor[NN];
__device__ int    g_bsum[128];
__device__ int    g_eidx[EMAX];
__device__ __half g_h16[(size_t)NN * FD];   // feat * norm_src (fp16), for gather
__device__ __half g_a16[(size_t)NN * FD];   // agg (fp16), A of GCN gemm
__device__ __half g_f16[(size_t)NN * FD];   // raw feat (fp16), A of skip gemm
// W and skip_W fragments INTERLEAVED:
// g_WS16[kcp*258 + n] = uint4{ W:half2(k0,k0+1), W:half2(k0+8,k0+9),
//                              S:half2(k0,k0+1), S:half2(k0+8,k0+9) }
// kcp = kc*4+p0, k0 = kc*16+p0*2; rows padded 256->258 (stride 4128 B in smem).
__device__ uint4  g_WS16[32 * 258];

// ---------------------------------------------------------------------------
// init: zero degrees; block 0 detects index width; blocks >= NB pack weights
__global__ void k_init(const int* __restrict__ srcw, const float* __restrict__ W,
                       const float* __restrict__ sW, int E, int N, int NB) {
    if ((int)blockIdx.x < NB) {
        int i = blockIdx.x * blockDim.x + threadIdx.x;
        if (i < N) { g_deg_out[i] = 0; g_deg_in[i] = 0; }
        if (blockIdx.x == 0) {
            __shared__ int bad;
            if (threadIdx.x == 0) bad = 0;
            __syncthreads();
            int n = E / 2; if (n > 256) n = 256;
            if ((int)threadIdx.x < n && srcw[2 * threadIdx.x + 1] != 0) bad = 1;
            __syncthreads();
            if (threadIdx.x == 0) g_is64 = (bad == 0);
        }
    } else {
        int i = (blockIdx.x - NB) * blockDim.x + threadIdx.x;  // 0..8191
        if (i < 32 * 256) {
            int kcp = i >> 8, n = i & 255;
            int kc = kcp >> 2, p0 = kcp & 3;
            int k0 = kc * 16 + p0 * 2;
            __half2 w0 = __floats2half2_rn(W[k0 * HD + n],       W[(k0 + 1) * HD + n]);
            __half2 w1 = __floats2half2_rn(W[(k0 + 8) * HD + n], W[(k0 + 9) * HD + n]);
            __half2 s0 = __floats2half2_rn(sW[k0 * HD + n],       sW[(k0 + 1) * HD + n]);
            __half2 s1 = __floats2half2_rn(sW[(k0 + 8) * HD + n], sW[(k0 + 9) * HD + n]);
            g_WS16[kcp * 258 + n] = make_uint4(*(unsigned*)&w0, *(unsigned*)&w1,
                                               *(unsigned*)&s0, *(unsigned*)&s1);
        }
    }
}

__device__ __forceinline__ int load_idx(const void* p, int i) {
    if (g_is64) return (int)((const long long*)p)[i];
    return ((const int*)p)[i];
}

__device__ __forceinline__ void load_pair(const void* p, int i, bool two,
                                          int& v0, int& v1) {
    if (g_is64) {
        if (two) {
            longlong2 v = *(const longlong2*)((const long long*)p + i);
            v0 = (int)v.x; v1 = (int)v.y;
        } else { v0 = (int)((const long long*)p)[i]; v1 = 0; }
    } else {
        if (two) {
            int2 v = *(const int2*)((const int*)p + i);
            v0 = v.x; v1 = v.y;
        } else { v0 = ((const int*)p)[i]; v1 = 0; }
    }
}

__global__ void k_count(const void* __restrict__ src, const void* __restrict__ dst, int E) {
    int i = (blockIdx.x * blockDim.x + threadIdx.x) * 2;
    if (i >= E) return;
    bool two = (i + 1 < E);
    int s0, s1, d0, d1;
    load_pair(src, i, two, s0, s1);
    load_pair(dst, i, two, d0, d1);
    atomicAdd(&g_deg_out[s0], 1);
    atomicAdd(&g_deg_in[d0], 1);
    if (two) {
        atomicAdd(&g_deg_out[s1], 1);
        atomicAdd(&g_deg_in[d1], 1);
    }
}

__global__ void k_scan1(int N) {
    __shared__ int s[1024];
    int tid = threadIdx.x;
    int i = blockIdx.x * 1024 + tid;
    int v = 0;
    if (i < N) {
        int din = g_deg_in[i];
        v = din;
        g_nsrc[i] = rsqrtf(fmaxf((float)g_deg_out[i], 1.0f));
        g_ndst[i] = rsqrtf(fmaxf((float)din, 1.0f));
    }
    s[tid] = v;
    for (int off = 1; off < 1024; off <<= 1) {
        __syncthreads();
        int t = (tid >= off) ? s[tid - off] : 0;
        __syncthreads();
        s[tid] += t;
    }
    __syncthreads();
    if (i < N) g_rowptr[i] = s[tid] - v;
    if (tid == 1023) g_bsum[blockIdx.x] = s[1023];
}

__global__ void k_scan3(int N, int E) {
    __shared__ int ssum;
    int tid = threadIdx.x;
    if (tid == 0) ssum = 0;
    __syncthreads();
    if (tid < blockIdx.x) atomicAdd(&ssum, g_bsum[tid]);
    __syncthreads();
    int i = blockIdx.x * 1024 + tid;
    if (i < N) {
        int val = g_rowptr[i] + ssum;
        g_rowptr[i] = val;
        g_cursor[i] = val;
    }
    if (i == 0) g_rowptr[N] = E;
}

// merged: blocks [0, FB) do CSR fill (1 edge/thread); blocks [FB,...) h16/f16 tables
__global__ void k_fill_h16(const void* __restrict__ src, const void* __restrict__ dst,
                           const float* __restrict__ feat, int E, int N, int FB) {
    if ((int)blockIdx.x < FB) {
        int i = blockIdx.x * blockDim.x + threadIdx.x;
        if (i < E) {
            int d = load_idx(dst, i);
            int pos = atomicAdd(&g_cursor[d], 1);
            g_eidx[pos] = load_idx(src, i);
        }
    } else {
        int i = (blockIdx.x - FB) * blockDim.x + threadIdx.x;
        if (i >= N * 8) return;
        int node = i >> 3, seg = i & 7;
        float ns = g_nsrc[node];
        const float4* fp = (const float4*)(feat + (size_t)node * FD + seg * 16);
        __half2 o[8], f[8];
#pragma unroll
        for (int j = 0; j < 4; j++) {
            float4 v = fp[j];
            o[j * 2]     = __floats2half2_rn(v.x * ns, v.y * ns);
            o[j * 2 + 1] = __floats2half2_rn(v.z * ns, v.w * ns);
            f[j * 2]     = __floats2half2_rn(v.x, v.y);
            f[j * 2 + 1] = __floats2half2_rn(v.z, v.w);
        }
        size_t off = (size_t)node * FD + seg * 16;
        *(uint4*)(g_h16 + off)     = *(uint4*)&o[0];
        *(uint4*)(g_h16 + off + 8) = *(uint4*)&o[4];
        *(uint4*)(g_f16 + off)     = *(uint4*)&f[0];
        *(uint4*)(g_f16 + off + 8) = *(uint4*)&f[4];
    }
}

// warp per node: a16[n] = fp16(norm_dst[n] * sum h16[src_e])
__global__ void k_gather(int N) {
    int w = (blockIdx.x * blockDim.x + threadIdx.x) >> 5;
    int lane = threadIdx.x & 31;
    if (w >= N) return;
    int beg = g_rowptr[w], end = g_rowptr[w + 1];
    float4 acc = make_float4(0.f, 0.f, 0.f, 0.f);
    for (int base = beg; base < end; base += 32) {
        int idx = base + lane;
        int mye = (idx < end) ? g_eidx[idx] : 0;
        int cnt = min(32, end - base);
        for (int i = 0; i < cnt; i++) {
            int s = __shfl_sync(0xffffffffu, mye, i);
            uint2 hv = *(const uint2*)(g_h16 + (size_t)s * FD + (lane << 2));
            float2 f0 = __half22float2(*(__half2*)&hv.x);
            float2 f1 = __half22float2(*(__half2*)&hv.y);
            acc.x += f0.x; acc.y += f0.y; acc.z += f1.x; acc.w += f1.y;
        }
    }
    float nd = g_ndst[w];
    __half2 o0 = __floats2half2_rn(acc.x * nd, acc.y * nd);
    __half2 o1 = __floats2half2_rn(acc.z * nd, acc.w * nd);
    uint2 ov = make_uint2(*(unsigned*)&o0, *(unsigned*)&o1);
    *(uint2*)(g_a16 + (size_t)w * FD + (lane << 2)) = ov;
}

// ---------------------------------------------------------------------------
__device__ __forceinline__ void mma_f16(float* c, unsigned a0, unsigned a1,
                                        unsigned a2, unsigned a3,
                                        unsigned b0, unsigned b1) {
    asm volatile(
        "mma.sync.aligned.m16n8k16.row.col.f32.f16.f16.f32 "
        "{%0,%1,%2,%3}, {%4,%5,%6,%7}, {%8,%9}, {%0,%1,%2,%3};"
        : "+f"(c[0]), "+f"(c[1]), "+f"(c[2]), "+f"(c[3])
        : "r"(a0), "r"(a1), "r"(a2), "r"(a3), "r"(b0), "r"(b1));
}

static __device__ __forceinline__ uint32_t smem_u32(const void* p) {
    uint32_t a;
    asm("{ .reg .u64 t; cvta.to.shared.u64 t, %1; cvt.u32.u64 %0, t; }"
        : "=r"(a) : "l"(p));
    return a;
}

// Persistent fused kernel smem layout (bytes):
//  B_ws [32 kcp][258 uint4] = 132096 at 0   (W+S interleaved, resident)
//  A buffers: 2 x { A_agg [64][272B], A_feat [64][272B] } = 2 x 34816
//  sLN  [64][4] float2 = 2048
#define BWS_OFF  0
#define BROW     4128                        // 258 * 16; mod 128 == 32 (conflict-free)
#define ABUF(b)  (132096 + (b) * 34816)
#define AG(b)    (ABUF(b))
#define AF(b)    (ABUF(b) + 17408)
#define SLN_OFF  201728
#define SMTOT    203776

// stage A for tile (64 rows x 128 halves, both matrices): 2048 16B chunks / 512 thr
__device__ __forceinline__ void stageA(uint32_t sb, int b, int tile, int N, int t) {
    int n0 = tile * 64;
#pragma unroll
    for (int j = 0; j < 4; j++) {
        int c = t + (j << 9);                 // 0..2047
        int mat = c >> 10, row = (c >> 4) & 63, seg = c & 15;
        int node = n0 + row;
        int sz = (node < N) ? 16 : 0;
        const __half* srcp = (mat ? g_f16 : g_a16) + (size_t)node * FD + seg * 8;
        uint32_t dst = sb + (mat ? AF(b) : AG(b)) + row * 272 + seg * 16;
        asm volatile("cp.async.cg.shared.global [%0], [%1], 16, %2;"
                     :: "r"(dst), "l"(srcp), "r"(sz));
    }
    asm volatile("cp.async.commit_group;");
}

// Persistent dual-GEMM + LN + ReLU + skip-add. grid=148, 512 threads, occ 1.
// Tile 64 rows x 256 cols; 16 warps = 4 row-groups x 4 col-groups; warp 16x64.
__global__ __launch_bounds__(512, 1)
void k_fused(const float* __restrict__ bias, const float* __restrict__ gamma,
             const float* __restrict__ beta, const float* __restrict__ sbias,
             float* __restrict__ out, int N, int ntiles)
{
    extern __shared__ char sm[];
    uint32_t sb = smem_u32(sm);
    int t = threadIdx.x;
    int lane = t & 31, wid = t >> 5;
    int wy = wid >> 2, wx = wid & 3;         // wy 0..3 rows, wx 0..3 cols
    int r0 = wy * 16 + (lane >> 2);
    int p0 = lane & 3;

    // ---- load interleaved weight array into smem once (8256 16B chunks) ----
#pragma unroll
    for (int j = 0; j < 17; j++) {
        int c = t + (j << 9);                 // 0..8703
        if (c < 32 * 258) {
            const uint4* srcp = g_WS16 + c;
            uint32_t dst = sb + BWS_OFF + c * 16;
            asm volatile("cp.async.ca.shared.global [%0], [%1], 16;"
                         :: "r"(dst), "l"(srcp));
        }
    }
    asm volatile("cp.async.commit_group;");

    int tile0 = blockIdx.x;
    if (tile0 < ntiles) stageA(sb, 0, tile0, N, t);
    else asm volatile("cp.async.commit_group;");

    const char* bws = sm + BWS_OFF;
    float2* sLN = (float2*)(sm + SLN_OFF);

    int it = 0;
    for (int tile = tile0; tile < ntiles; tile += gridDim.x, it++) {
        int b = it & 1;
        int nxt = tile + gridDim.x;
        if (nxt < ntiles) {
            stageA(sb, b ^ 1, nxt, N, t);
            asm volatile("cp.async.wait_group 1;");
        } else {
            asm volatile("cp.async.wait_group 0;");
        }
        __syncthreads();

        const char* ag = sm + AG(b);
        const char* af = sm + AF(b);

        float accG[8][4], accS[8][4];
#pragma unroll
        for (int i = 0; i < 8; i++)
#pragma unroll
            for (int j = 0; j < 4; j++) { accG[i][j] = 0.f; accS[i][j] = 0.f; }

#pragma unroll
        for (int kc = 0; kc < 8; kc++) {
            int ko = kc * 32 + p0 * 4;        // byte offset of half2(k0,k0+1)
            unsigned aG0 = *(const unsigned*)(ag + r0 * 272 + ko);
            unsigned aG1 = *(const unsigned*)(ag + (r0 + 8) * 272 + ko);
            unsigned aG2 = *(const unsigned*)(ag + r0 * 272 + ko + 16);
            unsigned aG3 = *(const unsigned*)(ag + (r0 + 8) * 272 + ko + 16);
            unsigned aF0 = *(const unsigned*)(af + r0 * 272 + ko);
            unsigned aF1 = *(const unsigned*)(af + (r0 + 8) * 272 + ko);
            unsigned aF2 = *(const unsigned*)(af + r0 * 272 + ko + 16);
            unsigned aF3 = *(const unsigned*)(af + (r0 + 8) * 272 + ko + 16);
            const char* brow = bws + (kc * 4 + p0) * BROW;
#pragma unroll
            for (int ni = 0; ni < 8; ni++) {
                int n = wx * 64 + ni * 8 + (lane >> 2);
                uint4 wv = *(const uint4*)(brow + n * 16);
                mma_f16(accG[ni], aG0, aG1, aG2, aG3, wv.x, wv.y);
                mma_f16(accS[ni], aF0, aF1, aF2, aF3, wv.z, wv.w);
            }
        }

        // ---- epilogue ----
        int colb = wx * 64 + 2 * p0;
#pragma unroll
        for (int ni = 0; ni < 8; ni++) {
            float2 bb = *(const float2*)(bias + colb + ni * 8);
            float2 sv = *(const float2*)(sbias + colb + ni * 8);
            accG[ni][0] += bb.x; accG[ni][1] += bb.y;
            accG[ni][2] += bb.x; accG[ni][3] += bb.y;
            accS[ni][0] += sv.x; accS[ni][1] += sv.y;
            accS[ni][2] += sv.x; accS[ni][3] += sv.y;
        }

        float s1 = 0.f, q1 = 0.f, s2 = 0.f, q2 = 0.f;
#pragma unroll
        for (int ni = 0; ni < 8; ni++) {
            s1 += accG[ni][0] + accG[ni][1];
            q1 += accG[ni][0] * accG[ni][0] + accG[ni][1] * accG[ni][1];
            s2 += accG[ni][2] + accG[ni][3];
            q2 += accG[ni][2] * accG[ni][2] + accG[ni][3] * accG[ni][3];
        }
#pragma unroll
        for (int off = 1; off <= 2; off <<= 1) {
            s1 += __shfl_xor_sync(0xffffffffu, s1, off);
            q1 += __shfl_xor_sync(0xffffffffu, q1, off);
            s2 += __shfl_xor_sync(0xffffffffu, s2, off);
            q2 += __shfl_xor_sync(0xffffffffu, q2, off);
        }
        if (p0 == 0) {
            sLN[r0 * 4 + wx] = make_float2(s1, q1);
            sLN[(r0 + 8) * 4 + wx] = make_float2(s2, q2);
        }
        __syncthreads();
        float2 t0 = sLN[r0 * 4 + 0], t1 = sLN[r0 * 4 + 1];
        float2 t2 = sLN[r0 * 4 + 2], t3 = sLN[r0 * 4 + 3];
        float mu1 = (t0.x + t1.x + t2.x + t3.x) * (1.0f / HD);
        float var1 = (t0.y + t1.y + t2.y + t3.y) * (1.0f / HD) - mu1 * mu1;
        float inv1 = rsqrtf(var1 + 1e-5f);
        float2 u0 = sLN[(r0 + 8) * 4 + 0], u1 = sLN[(r0 + 8) * 4 + 1];
        float2 u2 = sLN[(r0 + 8) * 4 + 2], u3 = sLN[(r0 + 8) * 4 + 3];
        float mu2 = (u0.x + u1.x + u2.x + u3.x) * (1.0f / HD);
        float var2 = (u0.y + u1.y + u2.y + u3.y) * (1.0f / HD) - mu2 * mu2;
        float inv2 = rsqrtf(var2 + 1e-5f);

        int node1 = tile * 64 + r0, node2 = node1 + 8;
#pragma unroll
        for (int ni = 0; ni < 8; ni++) {
            int col = colb + ni * 8;
            float2 gm = *(const float2*)(gamma + col);
            float2 bt = *(const float2*)(beta + col);
            if (node1 < N) {
                float2 o;
                o.x = fmaxf((accG[ni][0] - mu1) * inv1 * gm.x + bt.x, 0.f) + accS[ni][0];
                o.y = fmaxf((accG[ni][1] - mu1) * inv1 * gm.y + bt.y, 0.f) + accS[ni][1];
                *(float2*)(out + (size_t)node1 * HD + col) = o;
            }
            if (node2 < N) {
                float2 o;
                o.x = fmaxf((accG[ni][2] - mu2) * inv2 * gm.x + bt.x, 0.f) + accS[ni][2];
                o.y = fmaxf((accG[ni][3] - mu2) * inv2 * gm.y + bt.y, 0.f) + accS[ni][3];
                *(float2*)(out + (size_t)node2 * HD + col) = o;
            }
        }
        __syncthreads();   // protect A buffer b before next iteration stages into it
    }
}

// ---------------------------------------------------------------------------
extern "C" void kernel_launch(void* const* d_in, const int* in_sizes, int n_in,
                              void* d_out, int out_size)
{
    const float* feat = (const float*)d_in[0];
    const void*  src  = d_in[1];
    const void*  dst  = d_in[2];
    const float* Wm   = (const float*)d_in[3];
    const float* bv   = (const float*)d_in[4];
    const float* gm   = (const float*)d_in[5];
    const float* bt   = (const float*)d_in[6];
    const float* sWm  = (const float*)d_in[7];
    const float* sbv  = (const float*)d_in[8];
    float* out = (float*)d_out;

    int N = in_sizes[0] / FD;
    int E = in_sizes[1];
    int nb = (N + 1023) / 1024;
    int NB = (N + 255) / 256;
    int PB = (32 * 256 + 255) / 256;
    int FB = (E + 255) / 256;
    int HB = (N * 8 + 255) / 256;

    k_init<<<NB + PB, 256>>>((const int*)src, Wm, sWm, E, N, NB);
    k_count<<<(E / 2 + 255) / 256, 256>>>(src, dst, E);
    k_scan1<<<nb, 1024>>>(N);
    k_scan3<<<nb, 1024>>>(N, E);
    k_fill_h16<<<FB + HB, 256>>>(src, dst, feat, E, N, FB);
    k_gather<<<(N * 32 + 255) / 256, 256>>>(N);

    int ntiles = (N + 63) / 64;
    cudaFuncSetAttribute(k_fused, cudaFuncAttributeMaxDynamicSharedMemorySize, SMTOT);
    k_fused<<<148, 512, SMTOT>>>(bv, gm, bt, sbv, out, N, ntiles);
}

// round 15
// speedup vs baseline: 1.0136x; 1.0136x over previous
#include <cuda_runtime.h>
#include <cuda_fp16.h>
#include <stdint.h>

#define NN 100000
#define EMAX 1700000
#define FD 128
#define HD 256

// ---------------- scratch (__device__ globals; no allocs allowed) ----------
__device__ int    g_deg_out[NN];
__device__ int    g_deg_in[NN];
__device__ int    g_is64;
__device__ float  g_nsrc[NN];
__device__ float  g_ndst[NN];
__device__ int    g_rowptr[NN + 1];
__device__ int    g_cursor[NN];
__device__ int    g_bsum[128];
__device__ int    g_eidx[EMAX];
__device__ __half g_h16[(size_t)NN * FD];   // feat * norm_src (fp16): gather input AND skip-GEMM A
__device__ __half g_a16[(size_t)NN * FD];   // agg (fp16), A of GCN gemm
// B packed for m16n8k16: [(kc*4+p0)*256 + n] -> uint2{half2(k0,k0+1), half2(k0+8,k0+9)}
__device__ uint2  g_W16[32 * 256];
__device__ uint2  g_S16[32 * 256];

// ---------------------------------------------------------------------------
// init: zero degrees; block 0 detects index width; blocks >= NB pack weights
__global__ void k_init(const int* __restrict__ srcw, const float* __restrict__ W,
                       const float* __restrict__ sW, int E, int N, int NB) {
    if ((int)blockIdx.x < NB) {
        int i = blockIdx.x * blockDim.x + threadIdx.x;
        if (i < N) { g_deg_out[i] = 0; g_deg_in[i] = 0; }
        if (blockIdx.x == 0) {
            __shared__ int bad;
            if (threadIdx.x == 0) bad = 0;
            __syncthreads();
            int n = E / 2; if (n > 256) n = 256;
            if ((int)threadIdx.x < n && srcw[2 * threadIdx.x + 1] != 0) bad = 1;
            __syncthreads();
            if (threadIdx.x == 0) g_is64 = (bad == 0);
        }
    } else {
        int i = (blockIdx.x - NB) * blockDim.x + threadIdx.x;  // 0..8191
        if (i < 32 * 256) {
            int kc = i >> 10, p0 = (i >> 8) & 3, n = i & 255;
            int k0 = kc * 16 + p0 * 2;
            __half2 w0 = __floats2half2_rn(W[k0 * HD + n],       W[(k0 + 1) * HD + n]);
            __half2 w1 = __floats2half2_rn(W[(k0 + 8) * HD + n], W[(k0 + 9) * HD + n]);
            g_W16[i] = make_uint2(*(unsigned*)&w0, *(unsigned*)&w1);
            __half2 s0 = __floats2half2_rn(sW[k0 * HD + n],       sW[(k0 + 1) * HD + n]);
            __half2 s1 = __floats2half2_rn(sW[(k0 + 8) * HD + n], sW[(k0 + 9) * HD + n]);
            g_S16[i] = make_uint2(*(unsigned*)&s0, *(unsigned*)&s1);
        }
    }
}

__device__ __forceinline__ int load_idx(const void* p, int i) {
    if (g_is64) return (int)((const long long*)p)[i];
    return ((const int*)p)[i];
}

__device__ __forceinline__ void load_pair(const void* p, int i, bool two,
                                          int& v0, int& v1) {
    if (g_is64) {
        if (two) {
            longlong2 v = *(const longlong2*)((const long long*)p + i);
            v0 = (int)v.x; v1 = (int)v.y;
        } else { v0 = (int)((const long long*)p)[i]; v1 = 0; }
    } else {
        if (two) {
            int2 v = *(const int2*)((const int*)p + i);
            v0 = v.x; v1 = v.y;
        } else { v0 = ((const int*)p)[i]; v1 = 0; }
    }
}

__global__ void k_count(const void* __restrict__ src, const void* __restrict__ dst, int E) {
    int i = (blockIdx.x * blockDim.x + threadIdx.x) * 2;
    if (i >= E) return;
    bool two = (i + 1 < E);
    int s0, s1, d0, d1;
    load_pair(src, i, two, s0, s1);
    load_pair(dst, i, two, d0, d1);
    atomicAdd(&g_deg_out[s0], 1);
    atomicAdd(&g_deg_in[d0], 1);
    if (two) {
        atomicAdd(&g_deg_out[s1], 1);
        atomicAdd(&g_deg_in[d1], 1);
    }
}

__global__ void k_scan1(int N) {
    __shared__ int s[1024];
    int tid = threadIdx.x;
    int i = blockIdx.x * 1024 + tid;
    int v = 0;
    if (i < N) {
        int din = g_deg_in[i];
        v = din;
        g_nsrc[i] = rsqrtf(fmaxf((float)g_deg_out[i], 1.0f));
        g_ndst[i] = rsqrtf(fmaxf((float)din, 1.0f));
    }
    s[tid] = v;
    for (int off = 1; off < 1024; off <<= 1) {
        __syncthreads();
        int t = (tid >= off) ? s[tid - off] : 0;
        __syncthreads();
        s[tid] += t;
    }
    __syncthreads();
    if (i < N) g_rowptr[i] = s[tid] - v;
    if (tid == 1023) g_bsum[blockIdx.x] = s[1023];
}

__global__ void k_scan3(int N, int E) {
    __shared__ int ssum;
    int tid = threadIdx.x;
    if (tid == 0) ssum = 0;
    __syncthreads();
    if (tid < blockIdx.x) atomicAdd(&ssum, g_bsum[tid]);
    __syncthreads();
    int i = blockIdx.x * 1024 + tid;
    if (i < N) {
        int val = g_rowptr[i] + ssum;
        g_rowptr[i] = val;
        g_cursor[i] = val;
    }
    if (i == 0) g_rowptr[N] = E;
}

// merged: blocks [0, FB) do CSR fill (1 edge/thread); blocks [FB,...) h16 table
__global__ void k_fill_h16(const void* __restrict__ src, const void* __restrict__ dst,
                           const float* __restrict__ feat, int E, int N, int FB) {
    if ((int)blockIdx.x < FB) {
        int i = blockIdx.x * blockDim.x + threadIdx.x;
        if (i < E) {
            int d = load_idx(dst, i);
            int pos = atomicAdd(&g_cursor[d], 1);
            g_eidx[pos] = load_idx(src, i);
        }
    } else {
        int i = (blockIdx.x - FB) * blockDim.x + threadIdx.x;
        if (i >= N * 8) return;
        int node = i >> 3, seg = i & 7;
        float ns = g_nsrc[node];
        const float4* fp = (const float4*)(feat + (size_t)node * FD + seg * 16);
        __half2 o[8];
#pragma unroll
        for (int j = 0; j < 4; j++) {
            float4 v = fp[j];
            o[j * 2]     = __floats2half2_rn(v.x * ns, v.y * ns);
            o[j * 2 + 1] = __floats2half2_rn(v.z * ns, v.w * ns);
        }
        size_t off = (size_t)node * FD + seg * 16;
        *(uint4*)(g_h16 + off)     = *(uint4*)&o[0];
        *(uint4*)(g_h16 + off + 8) = *(uint4*)&o[4];
    }
}

// warp per node: a16[n] = fp16(norm_dst[n] * sum h16[src_e])
__global__ void k_gather(int N) {
    int w = (blockIdx.x * blockDim.x + threadIdx.x) >> 5;
    int lane = threadIdx.x & 31;
    if (w >= N) return;
    int beg = g_rowptr[w], end = g_rowptr[w + 1];
    float4 acc = make_float4(0.f, 0.f, 0.f, 0.f);
    for (int base = beg; base < end; base += 32) {
        int idx = base + lane;
        int mye = (idx < end) ? g_eidx[idx] : 0;
        int cnt = min(32, end - base);
        for (int i = 0; i < cnt; i++) {
            int s = __shfl_sync(0xffffffffu, mye, i);
            uint2 hv = *(const uint2*)(g_h16 + (size_t)s * FD + (lane << 2));
            float2 f0 = __half22float2(*(__half2*)&hv.x);
            float2 f1 = __half22float2(*(__half2*)&hv.y);
            acc.x += f0.x; acc.y += f0.y; acc.z += f1.x; acc.w += f1.y;
        }
    }
    float nd = g_ndst[w];
    __half2 o0 = __floats2half2_rn(acc.x * nd, acc.y * nd);
    __half2 o1 = __floats2half2_rn(acc.z * nd, acc.w * nd);
    uint2 ov = make_uint2(*(unsigned*)&o0, *(unsigned*)&o1);
    *(uint2*)(g_a16 + (size_t)w * FD + (lane << 2)) = ov;
}

// ---------------------------------------------------------------------------
__device__ __forceinline__ void mma_f16(float* c, unsigned a0, unsigned a1,
                                        unsigned a2, unsigned a3,
                                        unsigned b0, unsigned b1) {
    asm volatile(
        "mma.sync.aligned.m16n8k16.row.col.f32.f16.f16.f32 "
        "{%0,%1,%2,%3}, {%4,%5,%6,%7}, {%8,%9}, {%0,%1,%2,%3};"
        : "+f"(c[0]), "+f"(c[1]), "+f"(c[2]), "+f"(c[3])
        : "r"(a0), "r"(a1), "r"(a2), "r"(a3), "r"(b0), "r"(b1));
}

static __device__ __forceinline__ uint32_t smem_u32(const void* p) {
    uint32_t a;
    asm("{ .reg .u64 t; cvta.to.shared.u64 t, %1; cvt.u32.u64 %0, t; }"
        : "=r"(a) : "l"(p));
    return a;
}

// Persistent fused kernel smem layout (bytes):
//  B_w  [32][260 uint2] = 66560 at 0
//  B_s  66560 at 66560                         (weights resident, loaded once)
//  A buffers: 2 x { A_agg [64][272B], A_h16 [64][272B] } = 2 x 34816
//  sLN  [64][4] float2 = 2048
#define BW_OFF   0
#define BS_OFF   66560
#define ABUF(b)  (133120 + (b) * 34816)
#define AG(b)    (ABUF(b))
#define AF(b)    (ABUF(b) + 17408)
#define SLN_OFF  202752
#define SMTOT    204800

// stage A for tile (64 rows x 128 halves, both matrices): 2048 16B chunks / 512 thr
__device__ __forceinline__ void stageA(uint32_t sb, int b, int tile, int N, int t) {
    int n0 = tile * 64;
#pragma unroll
    for (int j = 0; j < 4; j++) {
        int c = t + (j << 9);                 // 0..2047
        int mat = c >> 10, row = (c >> 4) & 63, seg = c & 15;
        int node = n0 + row;
        int sz = (node < N) ? 16 : 0;
        const __half* srcp = (mat ? g_h16 : g_a16) + (size_t)node * FD + seg * 8;
        uint32_t dst = sb + (mat ? AF(b) : AG(b)) + row * 272 + seg * 16;
        asm volatile("cp.async.cg.shared.global [%0], [%1], 16, %2;"
                     :: "r"(dst), "l"(srcp), "r"(sz));
    }
    asm volatile("cp.async.commit_group;");
}

// Persistent dual-GEMM + LN + ReLU + skip-add. grid=148, 512 threads, occ 1.
// Tile 64 rows x 256 cols; 16 warps = 4 row-groups x 4 col-groups; warp 16x64.
// Skip GEMM uses h16 (= feat*nsrc) as A; epilogue rescales accS by 1/nsrc[row].
__global__ __launch_bounds__(512, 1)
void k_fused(const float* __restrict__ bias, const float* __restrict__ gamma,
             const float* __restrict__ beta, const float* __restrict__ sbias,
             float* __restrict__ out, int N, int ntiles)
{
    extern __shared__ char sm[];
    uint32_t sb = smem_u32(sm);
    int t = threadIdx.x;
    int lane = t & 31, wid = t >> 5;
    int wy = wid >> 2, wx = wid & 3;         // wy 0..3 rows, wx 0..3 cols
    int r0 = wy * 16 + (lane >> 2);
    int p0 = lane & 3;

    // ---- load both packed weight matrices into smem once (8192 chunks) ----
#pragma unroll
    for (int j = 0; j < 16; j++) {
        int c = t + (j << 9);                 // 0..8191
        int mat = c >> 12, r = (c >> 7) & 31, col2 = (c & 127) * 2;
        const uint2* srcp = (mat ? g_S16 : g_W16) + r * 256 + col2;
        uint32_t dst = sb + (mat ? BS_OFF : BW_OFF) + r * 2080 + col2 * 8;
        asm volatile("cp.async.ca.shared.global [%0], [%1], 16;"
                     :: "r"(dst), "l"(srcp));
    }
    asm volatile("cp.async.commit_group;");

    int tile0 = blockIdx.x;
    if (tile0 < ntiles) stageA(sb, 0, tile0, N, t);
    else asm volatile("cp.async.commit_group;");

    const char* bw = sm + BW_OFF;
    const char* bs = sm + BS_OFF;
    float2* sLN = (float2*)(sm + SLN_OFF);

    int it = 0;
    for (int tile = tile0; tile < ntiles; tile += gridDim.x, it++) {
        int b = it & 1;
        int nxt = tile + gridDim.x;
        if (nxt < ntiles) {
            stageA(sb, b ^ 1, nxt, N, t);
            asm volatile("cp.async.wait_group 1;");
        } else {
            asm volatile("cp.async.wait_group 0;");
        }
        __syncthreads();

        const char* ag = sm + AG(b);
        const char* af = sm + AF(b);

        float accG[8][4], accS[8][4];
#pragma unroll
        for (int i = 0; i < 8; i++)
#pragma unroll
            for (int j = 0; j < 4; j++) { accG[i][j] = 0.f; accS[i][j] = 0.f; }

#pragma unroll
        for (int kc = 0; kc < 8; kc++) {
            int ko = kc * 32 + p0 * 4;        // byte offset of half2(k0,k0+1)
            unsigned aG0 = *(const unsigned*)(ag + r0 * 272 + ko);
            unsigned aG1 = *(const unsigned*)(ag + (r0 + 8) * 272 + ko);
            unsigned aG2 = *(const unsigned*)(ag + r0 * 272 + ko + 16);
            unsigned aG3 = *(const unsigned*)(ag + (r0 + 8) * 272 + ko + 16);
            unsigned aF0 = *(const unsigned*)(af + r0 * 272 + ko);
            unsigned aF1 = *(const unsigned*)(af + (r0 + 8) * 272 + ko);
            unsigned aF2 = *(const unsigned*)(af + r0 * 272 + ko + 16);
            unsigned aF3 = *(const unsigned*)(af + (r0 + 8) * 272 + ko + 16);
#pragma unroll
            for (int ni = 0; ni < 8; ni++) {
                int n = wx * 64 + ni * 8 + (lane >> 2);
                uint2 wv = *(const uint2*)(bw + (kc * 4 + p0) * 2080 + n * 8);
                mma_f16(accG[ni], aG0, aG1, aG2, aG3, wv.x, wv.y);
                uint2 sv = *(const uint2*)(bs + (kc * 4 + p0) * 2080 + n * 8);
                mma_f16(accS[ni], aF0, aF1, aF2, aF3, sv.x, sv.y);
            }
        }

        // ---- epilogue ----
        int colb = wx * 64 + 2 * p0;
        int node1 = tile * 64 + r0, node2 = node1 + 8;

        // rescale skip product: feat = h16 / nsrc  (row scalar)
        float inv1s = (node1 < N) ? (1.0f / g_nsrc[node1]) : 0.f;
        float inv2s = (node2 < N) ? (1.0f / g_nsrc[node2]) : 0.f;

#pragma unroll
        for (int ni = 0; ni < 8; ni++) {
            float2 bb = *(const float2*)(bias + colb + ni * 8);
            float2 sv = *(const float2*)(sbias + colb + ni * 8);
            accG[ni][0] += bb.x; accG[ni][1] += bb.y;
            accG[ni][2] += bb.x; accG[ni][3] += bb.y;
            accS[ni][0] = accS[ni][0] * inv1s + sv.x;
            accS[ni][1] = accS[ni][1] * inv1s + sv.y;
            accS[ni][2] = accS[ni][2] * inv2s + sv.x;
            accS[ni][3] = accS[ni][3] * inv2s + sv.y;
        }

        float s1 = 0.f, q1 = 0.f, s2 = 0.f, q2 = 0.f;
#pragma unroll
        for (int ni = 0; ni < 8; ni++) {
            s1 += accG[ni][0] + accG[ni][1];
            q1 += accG[ni][0] * accG[ni][0] + accG[ni][1] * accG[ni][1];
            s2 += accG[ni][2] + accG[ni][3];
            q2 += accG[ni][2] * accG[ni][2] + accG[ni][3] * accG[ni][3];
        }
#pragma unroll
        for (int off = 1; off <= 2; off <<= 1) {
            s1 += __shfl_xor_sync(0xffffffffu, s1, off);
            q1 += __shfl_xor_sync(0xffffffffu, q1, off);
            s2 += __shfl_xor_sync(0xffffffffu, s2, off);
            q2 += __shfl_xor_sync(0xffffffffu, q2, off);
        }
        if (p0 == 0) {
            sLN[r0 * 4 + wx] = make_float2(s1, q1);
            sLN[(r0 + 8) * 4 + wx] = make_float2(s2, q2);
        }
        __syncthreads();
        float2 t0 = sLN[r0 * 4 + 0], t1 = sLN[r0 * 4 + 1];
        float2 t2 = sLN[r0 * 4 + 2], t3 = sLN[r0 * 4 + 3];
        float mu1 = (t0.x + t1.x + t2.x + t3.x) * (1.0f / HD);
        float var1 = (t0.y + t1.y + t2.y + t3.y) * (1.0f / HD) - mu1 * mu1;
        float inv1 = rsqrtf(var1 + 1e-5f);
        float2 u0 = sLN[(r0 + 8) * 4 + 0], u1 = sLN[(r0 + 8) * 4 + 1];
        float2 u2 = sLN[(r0 + 8) * 4 + 2], u3 = sLN[(r0 + 8) * 4 + 3];
        float mu2 = (u0.x + u1.x + u2.x + u3.x) * (1.0f / HD);
        float var2 = (u0.y + u1.y + u2.y + u3.y) * (1.0f / HD) - mu2 * mu2;
        float inv2 = rsqrtf(var2 + 1e-5f);

#pragma unroll
        for (int ni = 0; ni < 8; ni++) {
            int col = colb + ni * 8;
            float2 gm = *(const float2*)(gamma + col);
            float2 bt = *(const float2*)(beta + col);
            if (node1 < N) {
                float2 o;
                o.x = fmaxf((accG[ni][0] - mu1) * inv1 * gm.x + bt.x, 0.f) + accS[ni][0];
                o.y = fmaxf((accG[ni][1] - mu1) * inv1 * gm.y + bt.y, 0.f) + accS[ni][1];
                *(float2*)(out + (size_t)node1 * HD + col) = o;
            }
            if (node2 < N) {
                float2 o;
                o.x = fmaxf((accG[ni][2] - mu2) * inv2 * gm.x + bt.x, 0.f) + accS[ni][2];
                o.y = fmaxf((accG[ni][3] - mu2) * inv2 * gm.y + bt.y, 0.f) + accS[ni][3];
                *(float2*)(out + (size_t)node2 * HD + col) = o;
            }
        }
        __syncthreads();   // protect A buffer b before next iteration stages into it
    }
}

// ---------------------------------------------------------------------------
extern "C" void kernel_launch(void* const* d_in, const int* in_sizes, int n_in,
                              void* d_out, int out_size)
{
    const float* feat = (const float*)d_in[0];
    const void*  src  = d_in[1];
    const void*  dst  = d_in[2];
    const float* Wm   = (const float*)d_in[3];
    const float* bv   = (const float*)d_in[4];
    const float* gm   = (const float*)d_in[5];
    const float* bt   = (const float*)d_in[6];
    const float* sWm  = (const float*)d_in[7];
    const float* sbv  = (const float*)d_in[8];
    float* out = (float*)d_out;

    int N = in_sizes[0] / FD;
    int E = in_sizes[1];
    int nb = (N + 1023) / 1024;
    int NB = (N + 255) / 256;
    int PB = (32 * 256 + 255) / 256;
    int FB = (E + 255) / 256;
    int HB = (N * 8 + 255) / 256;

    k_init<<<NB + PB, 256>>>((const int*)src, Wm, sWm, E, N, NB);
    k_count<<<(E / 2 + 255) / 256, 256>>>(src, dst, E);
    k_scan1<<<nb, 1024>>>(N);
    k_scan3<<<nb, 1024>>>(N, E);
    k_fill_h16<<<FB + HB, 256>>>(src, dst, feat, E, N, FB);
    k_gather<<<(N * 32 + 255) / 256, 256>>>(N);

    int ntiles = (N + 63) / 64;
    cudaFuncSetAttribute(k_fused, cudaFuncAttributeMaxDynamicSharedMemorySize, SMTOT);
    k_fused<<<148, 512, SMTOT>>>(bv, gm, bt, sbv, out, N, ntiles);
}

// round 16
// speedup vs baseline: 1.0456x; 1.0316x over previous
#include <cuda_runtime.h>
#include <cuda_fp16.h>
#include <stdint.h>

#define NN 100000
#define EMAX 1700000
#define FD 128
#define HD 256

// ---------------- scratch (__device__ globals; no allocs allowed) ----------
__device__ int    g_deg_out[NN];
__device__ int    g_deg_in[NN];
__device__ int    g_is64;
__device__ int    g_total;
__device__ float  g_nsrc[NN];
__device__ float  g_ndst[NN];
__device__ int    g_rs[NN];                 // CSR segment start per node
__device__ int    g_re[NN];                 // CSR segment end per node
__device__ int    g_cursor[NN];
__device__ int    g_eidx[EMAX];
__device__ __half g_h16[(size_t)NN * FD];   // feat * norm_src (fp16), for gather
__device__ __half g_a16[(size_t)NN * FD];   // agg (fp16), A of GCN gemm
__device__ __half g_f16[(size_t)NN * FD];   // raw feat (fp16), A of skip gemm
// B packed for m16n8k16: [(kc*4+p0)*256 + n] -> uint2{half2(k0,k0+1), half2(k0+8,k0+9)}
__device__ uint2  g_W16[32 * 256];
__device__ uint2  g_S16[32 * 256];

// ---------------------------------------------------------------------------
// init: zero degrees + g_total; block 0 detects index width; blocks >= NB pack weights
__global__ void k_init(const int* __restrict__ srcw, const float* __restrict__ W,
                       const float* __restrict__ sW, int E, int N, int NB) {
    if ((int)blockIdx.x < NB) {
        int i = blockIdx.x * blockDim.x + threadIdx.x;
        if (i < N) { g_deg_out[i] = 0; g_deg_in[i] = 0; }
        if (blockIdx.x == 0) {
            __shared__ int bad;
            if (threadIdx.x == 0) { bad = 0; g_total = 0; }
            __syncthreads();
            int n = E / 2; if (n > 256) n = 256;
            if ((int)threadIdx.x < n && srcw[2 * threadIdx.x + 1] != 0) bad = 1;
            __syncthreads();
            if (threadIdx.x == 0) g_is64 = (bad == 0);
        }
    } else {
        int i = (blockIdx.x - NB) * blockDim.x + threadIdx.x;  // 0..8191
        if (i < 32 * 256) {
            int kc = i >> 10, p0 = (i >> 8) & 3, n = i & 255;
            int k0 = kc * 16 + p0 * 2;
            __half2 w0 = __floats2half2_rn(W[k0 * HD + n],       W[(k0 + 1) * HD + n]);
            __half2 w1 = __floats2half2_rn(W[(k0 + 8) * HD + n], W[(k0 + 9) * HD + n]);
            g_W16[i] = make_uint2(*(unsigned*)&w0, *(unsigned*)&w1);
            __half2 s0 = __floats2half2_rn(sW[k0 * HD + n],       sW[(k0 + 1) * HD + n]);
            __half2 s1 = __floats2half2_rn(sW[(k0 + 8) * HD + n], sW[(k0 + 9) * HD + n]);
            g_S16[i] = make_uint2(*(unsigned*)&s0, *(unsigned*)&s1);
        }
    }
}

__device__ __forceinline__ int load_idx(const void* p, int i) {
    if (g_is64) return (int)((const long long*)p)[i];
    return ((const int*)p)[i];
}

__device__ __forceinline__ void load_pair(const void* p, int i, bool two,
                                          int& v0, int& v1) {
    if (g_is64) {
        if (two) {
            longlong2 v = *(const longlong2*)((const long long*)p + i);
            v0 = (int)v.x; v1 = (int)v.y;
        } else { v0 = (int)((const long long*)p)[i]; v1 = 0; }
    } else {
        if (two) {
            int2 v = *(const int2*)((const int*)p + i);
            v0 = v.x; v1 = v.y;
        } else { v0 = ((const int*)p)[i]; v1 = 0; }
    }
}

__global__ void k_count(const void* __restrict__ src, const void* __restrict__ dst, int E) {
    int i = (blockIdx.x * blockDim.x + threadIdx.x) * 2;
    if (i >= E) return;
    bool two = (i + 1 < E);
    int s0, s1, d0, d1;
    load_pair(src, i, two, s0, s1);
    load_pair(dst, i, two, d0, d1);
    atomicAdd(&g_deg_out[s0], 1);
    atomicAdd(&g_deg_in[d0], 1);
    if (two) {
        atomicAdd(&g_deg_out[s1], 1);
        atomicAdd(&g_deg_in[d1], 1);
    }
}

// merged scan: block-local inclusive scan + atomic base reservation.
// Emits per-node [rs, re) CSR ranges (block bases in arrival order — valid,
// since gather reads both ends and intra-node order is already unordered).
// Also computes both norms.
__global__ void k_scanm(int N) {
    __shared__ int s[1024];
    __shared__ int base;
    int tid = threadIdx.x;
    int i = blockIdx.x * 1024 + tid;
    int v = 0;
    if (i < N) {
        int din = g_deg_in[i];
        v = din;
        g_nsrc[i] = rsqrtf(fmaxf((float)g_deg_out[i], 1.0f));
        g_ndst[i] = rsqrtf(fmaxf((float)din, 1.0f));
    }
    s[tid] = v;
    for (int off = 1; off < 1024; off <<= 1) {
        __syncthreads();
        int t = (tid >= off) ? s[tid - off] : 0;
        __syncthreads();
        s[tid] += t;
    }
    __syncthreads();
    if (tid == 1023) base = atomicAdd(&g_total, s[1023]);
    __syncthreads();
    if (i < N) {
        int e = base + s[tid];
        g_rs[i] = e - v;
        g_re[i] = e;
        g_cursor[i] = e - v;
    }
}

// merged: blocks [0, FB) do CSR fill (1 edge/thread); blocks [FB,...) h16/f16 tables
__global__ void k_fill_h16(const void* __restrict__ src, const void* __restrict__ dst,
                           const float* __restrict__ feat, int E, int N, int FB) {
    if ((int)blockIdx.x < FB) {
        int i = blockIdx.x * blockDim.x + threadIdx.x;
        if (i < E) {
            int d = load_idx(dst, i);
            int pos = atomicAdd(&g_cursor[d], 1);
            g_eidx[pos] = load_idx(src, i);
        }
    } else {
        int i = (blockIdx.x - FB) * blockDim.x + threadIdx.x;
        if (i >= N * 8) return;
        int node = i >> 3, seg = i & 7;
        float ns = g_nsrc[node];
        const float4* fp = (const float4*)(feat + (size_t)node * FD + seg * 16);
        __half2 o[8], f[8];
#pragma unroll
        for (int j = 0; j < 4; j++) {
            float4 v = fp[j];
            o[j * 2]     = __floats2half2_rn(v.x * ns, v.y * ns);
            o[j * 2 + 1] = __floats2half2_rn(v.z * ns, v.w * ns);
            f[j * 2]     = __floats2half2_rn(v.x, v.y);
            f[j * 2 + 1] = __floats2half2_rn(v.z, v.w);
        }
        size_t off = (size_t)node * FD + seg * 16;
        *(uint4*)(g_h16 + off)     = *(uint4*)&o[0];
        *(uint4*)(g_h16 + off + 8) = *(uint4*)&o[4];
        *(uint4*)(g_f16 + off)     = *(uint4*)&f[0];
        *(uint4*)(g_f16 + off + 8) = *(uint4*)&f[4];
    }
}

// warp per node: a16[n] = fp16(norm_dst[n] * sum h16[src_e])
__global__ void k_gather(int N) {
    int w = (blockIdx.x * blockDim.x + threadIdx.x) >> 5;
    int lane = threadIdx.x & 31;
    if (w >= N) return;
    int beg = g_rs[w], end = g_re[w];
    float4 acc = make_float4(0.f, 0.f, 0.f, 0.f);
    for (int base = beg; base < end; base += 32) {
        int idx = base + lane;
        int mye = (idx < end) ? g_eidx[idx] : 0;
        int cnt = min(32, end - base);
        for (int i = 0; i < cnt; i++) {
            int s = __shfl_sync(0xffffffffu, mye, i);
            uint2 hv = *(const uint2*)(g_h16 + (size_t)s * FD + (lane << 2));
            float2 f0 = __half22float2(*(__half2*)&hv.x);
            float2 f1 = __half22float2(*(__half2*)&hv.y);
            acc.x += f0.x; acc.y += f0.y; acc.z += f1.x; acc.w += f1.y;
        }
    }
    float nd = g_ndst[w];
    __half2 o0 = __floats2half2_rn(acc.x * nd, acc.y * nd);
    __half2 o1 = __floats2half2_rn(acc.z * nd, acc.w * nd);
    uint2 ov = make_uint2(*(unsigned*)&o0, *(unsigned*)&o1);
    *(uint2*)(g_a16 + (size_t)w * FD + (lane << 2)) = ov;
}

// ---------------------------------------------------------------------------
__device__ __forceinline__ void mma_f16(float* c, unsigned a0, unsigned a1,
                                        unsigned a2, unsigned a3,
                                        unsigned b0, unsigned b1) {
    asm volatile(
        "mma.sync.aligned.m16n8k16.row.col.f32.f16.f16.f32 "
        "{%0,%1,%2,%3}, {%4,%5,%6,%7}, {%8,%9}, {%0,%1,%2,%3};"
        : "+f"(c[0]), "+f"(c[1]), "+f"(c[2]), "+f"(c[3])
        : "r"(a0), "r"(a1), "r"(a2), "r"(a3), "r"(b0), "r"(b1));
}

static __device__ __forceinline__ uint32_t smem_u32(const void* p) {
    uint32_t a;
    asm("{ .reg .u64 t; cvta.to.shared.u64 t, %1; cvt.u32.u64 %0, t; }"
        : "=r"(a) : "l"(p));
    return a;
}

// Persistent fused kernel smem layout (bytes):
//  B_w  [32][260 uint2] = 66560 at 0
//  B_s  66560 at 66560                         (weights resident, loaded once)
//  A buffers: 2 x { A_agg [64][272B], A_feat [64][272B] } = 2 x 34816
//  sLN  [64][4] float2 = 2048
#define BW_OFF   0
#define BS_OFF   66560
#define ABUF(b)  (133120 + (b) * 34816)
#define AG(b)    (ABUF(b))
#define AF(b)    (ABUF(b) + 17408)
#define SLN_OFF  202752
#define SMTOT    204800

// stage A for tile (64 rows x 128 halves, both matrices): 2048 16B chunks / 512 thr
__device__ __forceinline__ void stageA(uint32_t sb, int b, int tile, int N, int t) {
    int n0 = tile * 64;
#pragma unroll
    for (int j = 0; j < 4; j++) {
        int c = t + (j << 9);                 // 0..2047
        int mat = c >> 10, row = (c >> 4) & 63, seg = c & 15;
        int node = n0 + row;
        int sz = (node < N) ? 16 : 0;
        const __half* srcp = (mat ? g_f16 : g_a16) + (size_t)node * FD + seg * 8;
        uint32_t dst = sb + (mat ? AF(b) : AG(b)) + row * 272 + seg * 16;
        asm volatile("cp.async.cg.shared.global [%0], [%1], 16, %2;"
                     :: "r"(dst), "l"(srcp), "r"(sz));
    }
    asm volatile("cp.async.commit_group;");
}

// Persistent dual-GEMM + LN + ReLU + skip-add. grid=148, 512 threads, occ 1.
// Tile 64 rows x 256 cols; 16 warps = 4 row-groups x 4 col-groups; warp 16x64.
__global__ __launch_bounds__(512, 1)
void k_fused(const float* __restrict__ bias, const float* __restrict__ gamma,
             const float* __restrict__ beta, const float* __restrict__ sbias,
             float* __restrict__ out, int N, int ntiles)
{
    extern __shared__ char sm[];
    uint32_t sb = smem_u32(sm);
    int t = threadIdx.x;
    int lane = t & 31, wid = t >> 5;
    int wy = wid >> 2, wx = wid & 3;         // wy 0..3 rows, wx 0..3 cols
    int r0 = wy * 16 + (lane >> 2);
    int p0 = lane & 3;

    // ---- load both packed weight matrices into smem once (8192 chunks) ----
#pragma unroll
    for (int j = 0; j < 16; j++) {
        int c = t + (j << 9);                 // 0..8191
        int mat = c >> 12, r = (c >> 7) & 31, col2 = (c & 127) * 2;
        const uint2* srcp = (mat ? g_S16 : g_W16) + r * 256 + col2;
        uint32_t dst = sb + (mat ? BS_OFF : BW_OFF) + r * 2080 + col2 * 8;
        asm volatile("cp.async.ca.shared.global [%0], [%1], 16;"
                     :: "r"(dst), "l"(srcp));
    }
    asm volatile("cp.async.commit_group;");

    int tile0 = blockIdx.x;
    if (tile0 < ntiles) stageA(sb, 0, tile0, N, t);
    else asm volatile("cp.async.commit_group;");

    const char* bw = sm + BW_OFF;
    const char* bs = sm + BS_OFF;
    float2* sLN = (float2*)(sm + SLN_OFF);

    int it = 0;
    for (int tile = tile0; tile < ntiles; tile += gridDim.x, it++) {
        int b = it & 1;
        int nxt = tile + gridDim.x;
        if (nxt < ntiles) {
            stageA(sb, b ^ 1, nxt, N, t);
            asm volatile("cp.async.wait_group 1;");
        } else {
            asm volatile("cp.async.wait_group 0;");
        }
        __syncthreads();

        const char* ag = sm + AG(b);
        const char* af = sm + AF(b);

        float accG[8][4], accS[8][4];
#pragma unroll
        for (int i = 0; i < 8; i++)
#pragma unroll
            for (int j = 0; j < 4; j++) { accG[i][j] = 0.f; accS[i][j] = 0.f; }

#pragma unroll
        for (int kc = 0; kc < 8; kc++) {
            int ko = kc * 32 + p0 * 4;        // byte offset of half2(k0,k0+1)
            unsigned aG0 = *(const unsigned*)(ag + r0 * 272 + ko);
            unsigned aG1 = *(const unsigned*)(ag + (r0 + 8) * 272 + ko);
            unsigned aG2 = *(const unsigned*)(ag + r0 * 272 + ko + 16);
            unsigned aG3 = *(const unsigned*)(ag + (r0 + 8) * 272 + ko + 16);
            unsigned aF0 = *(const unsigned*)(af + r0 * 272 + ko);
            unsigned aF1 = *(const unsigned*)(af + (r0 + 8) * 272 + ko);
            unsigned aF2 = *(const unsigned*)(af + r0 * 272 + ko + 16);
            unsigned aF3 = *(const unsigned*)(af + (r0 + 8) * 272 + ko + 16);
#pragma unroll
            for (int ni = 0; ni < 8; ni++) {
                int n = wx * 64 + ni * 8 + (lane >> 2);
                uint2 wv = *(const uint2*)(bw + (kc * 4 + p0) * 2080 + n * 8);
                mma_f16(accG[ni], aG0, aG1, aG2, aG3, wv.x, wv.y);
                uint2 sv = *(const uint2*)(bs + (kc * 4 + p0) * 2080 + n * 8);
                mma_f16(accS[ni], aF0, aF1, aF2, aF3, sv.x, sv.y);
            }
        }

        // ---- epilogue ----
        int colb = wx * 64 + 2 * p0;
#pragma unroll
        for (int ni = 0; ni < 8; ni++) {
            float2 bb = *(const float2*)(bias + colb + ni * 8);
            float2 sv = *(const float2*)(sbias + colb + ni * 8);
            accG[ni][0] += bb.x; accG[ni][1] += bb.y;
            accG[ni][2] += bb.x; accG[ni][3] += bb.y;
            accS[ni][0] += sv.x; accS[ni][1] += sv.y;
            accS[ni][2] += sv.x; accS[ni][3] += sv.y;
        }

        float s1 = 0.f, q1 = 0.f, s2 = 0.f, q2 = 0.f;
#pragma unroll
        for (int ni = 0; ni < 8; ni++) {
            s1 += accG[ni][0] + accG[ni][1];
            q1 += accG[ni][0] * accG[ni][0] + accG[ni][1] * accG[ni][1];
            s2 += accG[ni][2] + accG[ni][3];
            q2 += accG[ni][2] * accG[ni][2] + accG[ni][3] * accG[ni][3];
        }
#pragma unroll
        for (int off = 1; off <= 2; off <<= 1) {
            s1 += __shfl_xor_sync(0xffffffffu, s1, off);
            q1 += __shfl_xor_sync(0xffffffffu, q1, off);
            s2 += __shfl_xor_sync(0xffffffffu, s2, off);
            q2 += __shfl_xor_sync(0xffffffffu, q2, off);
        }
        if (p0 == 0) {
            sLN[r0 * 4 + wx] = make_float2(s1, q1);
            sLN[(r0 + 8) * 4 + wx] = make_float2(s2, q2);
        }
        __syncthreads();
        float2 t0 = sLN[r0 * 4 + 0], t1 = sLN[r0 * 4 + 1];
        float2 t2 = sLN[r0 * 4 + 2], t3 = sLN[r0 * 4 + 3];
        float mu1 = (t0.x + t1.x + t2.x + t3.x) * (1.0f / HD);
        float var1 = (t0.y + t1.y + t2.y + t3.y) * (1.0f / HD) - mu1 * mu1;
        float inv1 = rsqrtf(var1 + 1e-5f);
        float2 u0 = sLN[(r0 + 8) * 4 + 0], u1 = sLN[(r0 + 8) * 4 + 1];
        float2 u2 = sLN[(r0 + 8) * 4 + 2], u3 = sLN[(r0 + 8) * 4 + 3];
        float mu2 = (u0.x + u1.x + u2.x + u3.x) * (1.0f / HD);
        float var2 = (u0.y + u1.y + u2.y + u3.y) * (1.0f / HD) - mu2 * mu2;
        float inv2 = rsqrtf(var2 + 1e-5f);

        int node1 = tile * 64 + r0, node2 = node1 + 8;
#pragma unroll
        for (int ni = 0; ni < 8; ni++) {
            int col = colb + ni * 8;
            float2 gm = *(const float2*)(gamma + col);
            float2 bt = *(const float2*)(beta + col);
            if (node1 < N) {
                float2 o;
                o.x = fmaxf((accG[ni][0] - mu1) * inv1 * gm.x + bt.x, 0.f) + accS[ni][0];
                o.y = fmaxf((accG[ni][1] - mu1) * inv1 * gm.y + bt.y, 0.f) + accS[ni][1];
                *(float2*)(out + (size_t)node1 * HD + col) = o;
            }
            if (node2 < N) {
                float2 o;
                o.x = fmaxf((accG[ni][2] - mu2) * inv2 * gm.x + bt.x, 0.f) + accS[ni][2];
                o.y = fmaxf((accG[ni][3] - mu2) * inv2 * gm.y + bt.y, 0.f) + accS[ni][3];
                *(float2*)(out + (size_t)node2 * HD + col) = o;
            }
        }
        __syncthreads();   // protect A buffer b before next iteration stages into it
    }
}

// ---------------------------------------------------------------------------
extern "C" void kernel_launch(void* const* d_in, const int* in_sizes, int n_in,
                              void* d_out, int out_size)
{
    const float* feat = (const float*)d_in[0];
    const void*  src  = d_in[1];
    const void*  dst  = d_in[2];
    const float* Wm   = (const float*)d_in[3];
    const float* bv   = (const float*)d_in[4];
    const float* gm   = (const float*)d_in[5];
    const float* bt   = (const float*)d_in[6];
    const float* sWm  = (const float*)d_in[7];
    const float* sbv  = (const float*)d_in[8];
    float* out = (float*)d_out;

    int N = in_sizes[0] / FD;
    int E = in_sizes[1];
    int nb = (N + 1023) / 1024;
    int NB = (N + 255) / 256;
    int PB = (32 * 256 + 255) / 256;
    int FB = (E + 255) / 256;
    int HB = (N * 8 + 255) / 256;

    k_init<<<NB + PB, 256>>>((const int*)src, Wm, sWm, E, N, NB);
    k_count<<<(E / 2 + 255) / 256, 256>>>(src, dst, E);
    k_scanm<<<nb, 1024>>>(N);
    k_fill_h16<<<FB + HB, 256>>>(src, dst, feat, E, N, FB);
    k_gather<<<(N * 32 + 255) / 256, 256>>>(N);

    int ntiles = (N + 63) / 64;
    cudaFuncSetAttribute(k_fused, cudaFuncAttributeMaxDynamicSharedMemorySize, SMTOT);
    k_fused<<<148, 512, SMTOT>>>(bv, gm, bt, sbv, out, N, ntiles);
}

// round 17
// speedup vs baseline: 1.0460x; 1.0004x over previous
#include <cuda_runtime.h>
#include <cuda_fp16.h>
#include <stdint.h>

#define NN 100000
#define EMAX 1700000
#define FD 128
#define HD 256

// ---------------- scratch (__device__ globals; no allocs allowed) ----------
__device__ int    g_deg_out[NN];
__device__ int    g_deg_in[NN];
__device__ int    g_is64;
__device__ int    g_total;
__device__ float  g_nsrc[NN];
__device__ float  g_ndst[NN];
__device__ int    g_rs[NN];                 // CSR segment start per node
__device__ int    g_re[NN];                 // CSR segment end per node
__device__ int    g_cursor[NN];
__device__ int    g_eidx[EMAX];
__device__ __half g_a16[(size_t)NN * FD];   // agg (fp16), A of GCN gemm
__device__ __half g_f16[(size_t)NN * FD];   // raw feat (fp16): gather input AND skip-GEMM A
// B packed for m16n8k16: [(kc*4+p0)*256 + n] -> uint2{half2(k0,k0+1), half2(k0+8,k0+9)}
__device__ uint2  g_W16[32 * 256];
__device__ uint2  g_S16[32 * 256];

// ---------------------------------------------------------------------------
// init: zero degrees + g_total; block 0 detects index width; blocks >= NB pack weights
__global__ void k_init(const int* __restrict__ srcw, const float* __restrict__ W,
                       const float* __restrict__ sW, int E, int N, int NB) {
    if ((int)blockIdx.x < NB) {
        int i = blockIdx.x * blockDim.x + threadIdx.x;
        if (i < N) { g_deg_out[i] = 0; g_deg_in[i] = 0; }
        if (blockIdx.x == 0) {
            __shared__ int bad;
            if (threadIdx.x == 0) { bad = 0; g_total = 0; }
            __syncthreads();
            int n = E / 2; if (n > 256) n = 256;
            if ((int)threadIdx.x < n && srcw[2 * threadIdx.x + 1] != 0) bad = 1;
            __syncthreads();
            if (threadIdx.x == 0) g_is64 = (bad == 0);
        }
    } else {
        int i = (blockIdx.x - NB) * blockDim.x + threadIdx.x;  // 0..8191
        if (i < 32 * 256) {
            int kc = i >> 10, p0 = (i >> 8) & 3, n = i & 255;
            int k0 = kc * 16 + p0 * 2;
            __half2 w0 = __floats2half2_rn(W[k0 * HD + n],       W[(k0 + 1) * HD + n]);
            __half2 w1 = __floats2half2_rn(W[(k0 + 8) * HD + n], W[(k0 + 9) * HD + n]);
            g_W16[i] = make_uint2(*(unsigned*)&w0, *(unsigned*)&w1);
            __half2 s0 = __floats2half2_rn(sW[k0 * HD + n],       sW[(k0 + 1) * HD + n]);
            __half2 s1 = __floats2half2_rn(sW[(k0 + 8) * HD + n], sW[(k0 + 9) * HD + n]);
            g_S16[i] = make_uint2(*(unsigned*)&s0, *(unsigned*)&s1);
        }
    }
}

__device__ __forceinline__ int load_idx(const void* p, int i) {
    if (g_is64) return (int)((const long long*)p)[i];
    return ((const int*)p)[i];
}

__device__ __forceinline__ void load_pair(const void* p, int i, bool two,
                                          int& v0, int& v1) {
    if (g_is64) {
        if (two) {
            longlong2 v = *(const longlong2*)((const long long*)p + i);
            v0 = (int)v.x; v1 = (int)v.y;
        } else { v0 = (int)((const long long*)p)[i]; v1 = 0; }
    } else {
        if (two) {
            int2 v = *(const int2*)((const int*)p + i);
            v0 = v.x; v1 = v.y;
        } else { v0 = ((const int*)p)[i]; v1 = 0; }
    }
}

__global__ void k_count(const void* __restrict__ src, const void* __restrict__ dst, int E) {
    int i = (blockIdx.x * blockDim.x + threadIdx.x) * 2;
    if (i >= E) return;
    bool two = (i + 1 < E);
    int s0, s1, d0, d1;
    load_pair(src, i, two, s0, s1);
    load_pair(dst, i, two, d0, d1);
    atomicAdd(&g_deg_out[s0], 1);
    atomicAdd(&g_deg_in[d0], 1);
    if (two) {
        atomicAdd(&g_deg_out[s1], 1);
        atomicAdd(&g_deg_in[d1], 1);
    }
}

// merged scan: block-local inclusive scan + atomic base reservation.
// Emits per-node [rs, re) CSR ranges; also computes both norms.
__global__ void k_scanm(int N) {
    __shared__ int s[1024];
    __shared__ int base;
    int tid = threadIdx.x;
    int i = blockIdx.x * 1024 + tid;
    int v = 0;
    if (i < N) {
        int din = g_deg_in[i];
        v = din;
        g_nsrc[i] = rsqrtf(fmaxf((float)g_deg_out[i], 1.0f));
        g_ndst[i] = rsqrtf(fmaxf((float)din, 1.0f));
    }
    s[tid] = v;
    for (int off = 1; off < 1024; off <<= 1) {
        __syncthreads();
        int t = (tid >= off) ? s[tid - off] : 0;
        __syncthreads();
        s[tid] += t;
    }
    __syncthreads();
    if (tid == 1023) base = atomicAdd(&g_total, s[1023]);
    __syncthreads();
    if (i < N) {
        int e = base + s[tid];
        g_rs[i] = e - v;
        g_re[i] = e;
        g_cursor[i] = e - v;
    }
}

// merged: blocks [0, FB) do CSR fill (1 edge/thread); blocks [FB,...) f16 table
__global__ void k_fill_f16(const void* __restrict__ src, const void* __restrict__ dst,
                           const float* __restrict__ feat, int E, int N, int FB) {
    if ((int)blockIdx.x < FB) {
        int i = blockIdx.x * blockDim.x + threadIdx.x;
        if (i < E) {
            int d = load_idx(dst, i);
            int pos = atomicAdd(&g_cursor[d], 1);
            g_eidx[pos] = load_idx(src, i);
        }
    } else {
        int i = (blockIdx.x - FB) * blockDim.x + threadIdx.x;
        if (i >= N * 8) return;
        int node = i >> 3, seg = i & 7;
        const float4* fp = (const float4*)(feat + (size_t)node * FD + seg * 16);
        __half2 f[8];
#pragma unroll
        for (int j = 0; j < 4; j++) {
            float4 v = fp[j];
            f[j * 2]     = __floats2half2_rn(v.x, v.y);
            f[j * 2 + 1] = __floats2half2_rn(v.z, v.w);
        }
        size_t off = (size_t)node * FD + seg * 16;
        *(uint4*)(g_f16 + off)     = *(uint4*)&f[0];
        *(uint4*)(g_f16 + off + 8) = *(uint4*)&f[4];
    }
}

// warp per node: a16[n] = fp16(norm_dst[n] * sum nsrc[s] * f16[s])
// nsrc rides the same shfl broadcast as the edge index.
__global__ void k_gather(int N) {
    int w = (blockIdx.x * blockDim.x + threadIdx.x) >> 5;
    int lane = threadIdx.x & 31;
    if (w >= N) return;
    int beg = g_rs[w], end = g_re[w];
    float4 acc = make_float4(0.f, 0.f, 0.f, 0.f);
    for (int base = beg; base < end; base += 32) {
        int idx = base + lane;
        int mye = 0;
        float myns = 0.f;
        if (idx < end) {
            mye = g_eidx[idx];
            myns = g_nsrc[mye];
        }
        int cnt = min(32, end - base);
        for (int i = 0; i < cnt; i++) {
            int s = __shfl_sync(0xffffffffu, mye, i);
            float ns = __shfl_sync(0xffffffffu, myns, i);
            uint2 hv = *(const uint2*)(g_f16 + (size_t)s * FD + (lane << 2));
            float2 f0 = __half22float2(*(__half2*)&hv.x);
            float2 f1 = __half22float2(*(__half2*)&hv.y);
            acc.x = fmaf(f0.x, ns, acc.x);
            acc.y = fmaf(f0.y, ns, acc.y);
            acc.z = fmaf(f1.x, ns, acc.z);
            acc.w = fmaf(f1.y, ns, acc.w);
        }
    }
    float nd = g_ndst[w];
    __half2 o0 = __floats2half2_rn(acc.x * nd, acc.y * nd);
    __half2 o1 = __floats2half2_rn(acc.z * nd, acc.w * nd);
    uint2 ov = make_uint2(*(unsigned*)&o0, *(unsigned*)&o1);
    *(uint2*)(g_a16 + (size_t)w * FD + (lane << 2)) = ov;
}

// ---------------------------------------------------------------------------
__device__ __forceinline__ void mma_f16(float* c, unsigned a0, unsigned a1,
                                        unsigned a2, unsigned a3,
                                        unsigned b0, unsigned b1) {
    asm volatile(
        "mma.sync.aligned.m16n8k16.row.col.f32.f16.f16.f32 "
        "{%0,%1,%2,%3}, {%4,%5,%6,%7}, {%8,%9}, {%0,%1,%2,%3};"
        : "+f"(c[0]), "+f"(c[1]), "+f"(c[2]), "+f"(c[3])
        : "r"(a0), "r"(a1), "r"(a2), "r"(a3), "r"(b0), "r"(b1));
}

static __device__ __forceinline__ uint32_t smem_u32(const void* p) {
    uint32_t a;
    asm("{ .reg .u64 t; cvta.to.shared.u64 t, %1; cvt.u32.u64 %0, t; }"
        : "=r"(a) : "l"(p));
    return a;
}

// Persistent fused kernel smem layout (bytes):
//  B_w  [32][260 uint2] = 66560 at 0
//  B_s  66560 at 66560                         (weights resident, loaded once)
//  A buffers: 2 x { A_agg [64][272B], A_feat [64][272B] } = 2 x 34816
//  sLN  [64][4] float2 = 2048
#define BW_OFF   0
#define BS_OFF   66560
#define ABUF(b)  (133120 + (b) * 34816)
#define AG(b)    (ABUF(b))
#define AF(b)    (ABUF(b) + 17408)
#define SLN_OFF  202752
#define SMTOT    204800

// stage A for tile (64 rows x 128 halves, both matrices): 2048 16B chunks / 512 thr
__device__ __forceinline__ void stageA(uint32_t sb, int b, int tile, int N, int t) {
    int n0 = tile * 64;
#pragma unroll
    for (int j = 0; j < 4; j++) {
        int c = t + (j << 9);                 // 0..2047
        int mat = c >> 10, row = (c >> 4) & 63, seg = c & 15;
        int node = n0 + row;
        int sz = (node < N) ? 16 : 0;
        const __half* srcp = (mat ? g_f16 : g_a16) + (size_t)node * FD + seg * 8;
        uint32_t dst = sb + (mat ? AF(b) : AG(b)) + row * 272 + seg * 16;
        asm volatile("cp.async.cg.shared.global [%0], [%1], 16, %2;"
                     :: "r"(dst), "l"(srcp), "r"(sz));
    }
    asm volatile("cp.async.commit_group;");
}

// Persistent dual-GEMM + LN + ReLU + skip-add. grid=148, 512 threads, occ 1.
// Tile 64 rows x 256 cols; 16 warps = 4 row-groups x 4 col-groups; warp 16x64.
__global__ __launch_bounds__(512, 1)
void k_fused(const float* __restrict__ bias, const float* __restrict__ gamma,
             const float* __restrict__ beta, const float* __restrict__ sbias,
             float* __restrict__ out, int N, int ntiles)
{
    extern __shared__ char sm[];
    uint32_t sb = smem_u32(sm);
    int t = threadIdx.x;
    int lane = t & 31, wid = t >> 5;
    int wy = wid >> 2, wx = wid & 3;         // wy 0..3 rows, wx 0..3 cols
    int r0 = wy * 16 + (lane >> 2);
    int p0 = lane & 3;

    // ---- load both packed weight matrices into smem once (8192 chunks) ----
#pragma unroll
    for (int j = 0; j < 16; j++) {
        int c = t + (j << 9);                 // 0..8191
        int mat = c >> 12, r = (c >> 7) & 31, col2 = (c & 127) * 2;
        const uint2* srcp = (mat ? g_S16 : g_W16) + r * 256 + col2;
        uint32_t dst = sb + (mat ? BS_OFF : BW_OFF) + r * 2080 + col2 * 8;
        asm volatile("cp.async.ca.shared.global [%0], [%1], 16;"
                     :: "r"(dst), "l"(srcp));
    }
    asm volatile("cp.async.commit_group;");

    int tile0 = blockIdx.x;
    if (tile0 < ntiles) stageA(sb, 0, tile0, N, t);
    else asm volatile("cp.async.commit_group;");

    const char* bw = sm + BW_OFF;
    const char* bs = sm + BS_OFF;
    float2* sLN = (float2*)(sm + SLN_OFF);

    int it = 0;
    for (int tile = tile0; tile < ntiles; tile += gridDim.x, it++) {
        int b = it & 1;
        int nxt = tile + gridDim.x;
        if (nxt < ntiles) {
            stageA(sb, b ^ 1, nxt, N, t);
            asm volatile("cp.async.wait_group 1;");
        } else {
            asm volatile("cp.async.wait_group 0;");
        }
        __syncthreads();

        const char* ag = sm + AG(b);
        const char* af = sm + AF(b);

        float accG[8][4], accS[8][4];
#pragma unroll
        for (int i = 0; i < 8; i++)
#pragma unroll
            for (int j = 0; j < 4; j++) { accG[i][j] = 0.f; accS[i][j] = 0.f; }

#pragma unroll
        for (int kc = 0; kc < 8; kc++) {
            int ko = kc * 32 + p0 * 4;        // byte offset of half2(k0,k0+1)
            unsigned aG0 = *(const unsigned*)(ag + r0 * 272 + ko);
            unsigned aG1 = *(const unsigned*)(ag + (r0 + 8) * 272 + ko);
            unsigned aG2 = *(const unsigned*)(ag + r0 * 272 + ko + 16);
            unsigned aG3 = *(const unsigned*)(ag + (r0 + 8) * 272 + ko + 16);
            unsigned aF0 = *(const unsigned*)(af + r0 * 272 + ko);
            unsigned aF1 = *(const unsigned*)(af + (r0 + 8) * 272 + ko);
            unsigned aF2 = *(const unsigned*)(af + r0 * 272 + ko + 16);
            unsigned aF3 = *(const unsigned*)(af + (r0 + 8) * 272 + ko + 16);
#pragma unroll
            for (int ni = 0; ni < 8; ni++) {
                int n = wx * 64 + ni * 8 + (lane >> 2);
                uint2 wv = *(const uint2*)(bw + (kc * 4 + p0) * 2080 + n * 8);
                mma_f16(accG[ni], aG0, aG1, aG2, aG3, wv.x, wv.y);
                uint2 sv = *(const uint2*)(bs + (kc * 4 + p0) * 2080 + n * 8);
                mma_f16(accS[ni], aF0, aF1, aF2, aF3, sv.x, sv.y);
            }
        }

        // ---- epilogue ----
        int colb = wx * 64 + 2 * p0;
#pragma unroll
        for (int ni = 0; ni < 8; ni++) {
            float2 bb = *(const float2*)(bias + colb + ni * 8);
            float2 sv = *(const float2*)(sbias + colb + ni * 8);
            accG[ni][0] += bb.x; accG[ni][1] += bb.y;
            accG[ni][2] += bb.x; accG[ni][3] += bb.y;
            accS[ni][0] += sv.x; accS[ni][1] += sv.y;
            accS[ni][2] += sv.x; accS[ni][3] += sv.y;
        }

        float s1 = 0.f, q1 = 0.f, s2 = 0.f, q2 = 0.f;
#pragma unroll
        for (int ni = 0; ni < 8; ni++) {
            s1 += accG[ni][0] + accG[ni][1];
            q1 += accG[ni][0] * accG[ni][0] + accG[ni][1] * accG[ni][1];
            s2 += accG[ni][2] + accG[ni][3];
            q2 += accG[ni][2] * accG[ni][2] + accG[ni][3] * accG[ni][3];
        }
#pragma unroll
        for (int off = 1; off <= 2; off <<= 1) {
            s1 += __shfl_xor_sync(0xffffffffu, s1, off);
            q1 += __shfl_xor_sync(0xffffffffu, q1, off);
            s2 += __shfl_xor_sync(0xffffffffu, s2, off);
            q2 += __shfl_xor_sync(0xffffffffu, q2, off);
        }
        if (p0 == 0) {
            sLN[r0 * 4 + wx] = make_float2(s1, q1);
            sLN[(r0 + 8) * 4 + wx] = make_float2(s2, q2);
        }
        __syncthreads();
        float2 t0 = sLN[r0 * 4 + 0], t1 = sLN[r0 * 4 + 1];
        float2 t2 = sLN[r0 * 4 + 2], t3 = sLN[r0 * 4 + 3];
        float mu1 = (t0.x + t1.x + t2.x + t3.x) * (1.0f / HD);
        float var1 = (t0.y + t1.y + t2.y + t3.y) * (1.0f / HD) - mu1 * mu1;
        float inv1 = rsqrtf(var1 + 1e-5f);
        float2 u0 = sLN[(r0 + 8) * 4 + 0], u1 = sLN[(r0 + 8) * 4 + 1];
        float2 u2 = sLN[(r0 + 8) * 4 + 2], u3 = sLN[(r0 + 8) * 4 + 3];
        float mu2 = (u0.x + u1.x + u2.x + u3.x) * (1.0f / HD);
        float var2 = (u0.y + u1.y + u2.y + u3.y) * (1.0f / HD) - mu2 * mu2;
        float inv2 = rsqrtf(var2 + 1e-5f);

        int node1 = tile * 64 + r0, node2 = node1 + 8;
#pragma unroll
        for (int ni = 0; ni < 8; ni++) {
            int col = colb + ni * 8;
            float2 gm = *(const float2*)(gamma + col);
            float2 bt = *(const float2*)(beta + col);
            if (node1 < N) {
                float2 o;
                o.x = fmaxf((accG[ni][0] - mu1) * inv1 * gm.x + bt.x, 0.f) + accS[ni][0];
                o.y = fmaxf((accG[ni][1] - mu1) * inv1 * gm.y + bt.y, 0.f) + accS[ni][1];
                *(float2*)(out + (size_t)node1 * HD + col) = o;
            }
            if (node2 < N) {
                float2 o;
                o.x = fmaxf((accG[ni][2] - mu2) * inv2 * gm.x + bt.x, 0.f) + accS[ni][2];
                o.y = fmaxf((accG[ni][3] - mu2) * inv2 * gm.y + bt.y, 0.f) + accS[ni][3];
                *(float2*)(out + (size_t)node2 * HD + col) = o;
            }
        }
        __syncthreads();   // protect A buffer b before next iteration stages into it
    }
}

// ---------------------------------------------------------------------------
extern "C" void kernel_launch(void* const* d_in, const int* in_sizes, int n_in,
                              void* d_out, int out_size)
{
    const float* feat = (const float*)d_in[0];
    const void*  src  = d_in[1];
    const void*  dst  = d_in[2];
    const float* Wm   = (const float*)d_in[3];
    const float* bv   = (const float*)d_in[4];
    const float* gm   = (const float*)d_in[5];
    const float* bt   = (const float*)d_in[6];
    const float* sWm  = (const float*)d_in[7];
    const float* sbv  = (const float*)d_in[8];
    float* out = (float*)d_out;

    int N = in_sizes[0] / FD;
    int E = in_sizes[1];
    int nb = (N + 1023) / 1024;
    int NB = (N + 255) / 256;
    int PB = (32 * 256 + 255) / 256;
    int FB = (E + 255) / 256;
    int HB = (N * 8 + 255) / 256;

    k_init<<<NB + PB, 256>>>((const int*)src, Wm, sWm, E, N, NB);
    k_count<<<(E / 2 + 255) / 256, 256>>>(src, dst, E);
    k_scanm<<<nb, 1024>>>(N);
    k_fill_f16<<<FB + HB, 256>>>(src, dst, feat, E, N, FB);
    k_gather<<<(N * 32 + 255) / 256, 256>>>(N);

    int ntiles = (N + 63) / 64;
    cudaFuncSetAttribute(k_fused, cudaFuncAttributeMaxDynamicSharedMemorySize, SMTOT);
    k_fused<<<148, 512, SMTOT>>>(bv, gm, bt, sbv, out, N, ntiles);
}